// round 7
// baseline (speedup 1.0000x reference)
#include <cuda_runtime.h>
#include <cstdint>

// AdaptiveSparseVoxels: expand N parents -> 8N children.
// Output (float32): [8N x 32] row-major features, then 8N morton-as-float.
// Row layout: px py pz size dens c0..c26 (32 floats = 128B)
//
// R7 strategy: build each block's entire output tile in SMEM, then move it
// to GMEM with cp.async.bulk (shared::cta -> global, bulk_group). This takes
// the 268MB store stream off the per-warp STG/L1-wavefront path (R6 showed
// DRAM and L1 co-stuck at ~60%) and onto the TMA/async-proxy path which
// feeds L2 directly.
//
// Block = 16 parents = 128 child rows:
//   tile : 16*8*32 floats = 16KB (features, block-contiguous in gmem)
//   mort : 16*8 floats    = 512B (morton, block-contiguous in gmem)
// Phase A: warp-lane mapping j=lane&7 (column float4), rg=lane>>3; smem
//          writes are consecutive 16B per lane (conflict-free STS.128).
// Phase B: tid<128 -> one morton per thread, full-lane packed.
// Then one thread issues 2 bulk copies, commits, waits (.read) before exit.

#define TPB 256
#define WPB 8              // warps per block
#define WP  2              // parents per warp (phase A)
#define PPB (WPB * WP)     // 16 parents per block

__device__ __forceinline__ unsigned part1by2(unsigned n) {
    n &= 1023u;
    n = (n ^ (n << 16)) & 0xFF0000FFu;
    n = (n ^ (n << 8))  & 0x0300F00Fu;
    n = (n ^ (n << 4))  & 0x030C30C3u;
    n = (n ^ (n << 2))  & 0x09249249u;
    return n;
}

__device__ __forceinline__ unsigned coord_of(float p, float fres, int resm1) {
    // reference: ((p + 1) / 2 * res).astype(int32) then clip(0, res-1)
    float norm = __fmul_rn(__fmul_rn(__fadd_rn(p, 1.0f), 0.5f), fres);
    int c = (int)norm;                 // trunc toward zero == astype(int32)
    c = c < 0 ? 0 : (c > resm1 ? resm1 : c);
    return (unsigned)c;
}

__device__ __forceinline__ unsigned smem_u32(const void* p) {
    return (unsigned)__cvta_generic_to_shared(p);
}

__global__ void __launch_bounds__(TPB)
asv_expand_kernel(
    const float* __restrict__ positions,   // [N,3]
    const float* __restrict__ sizes,       // [N]
    const float* __restrict__ densities,   // [N]
    const float* __restrict__ colors,      // [N,27]
    const int*   __restrict__ level_p,     // [1]
    float*       __restrict__ out,         // [8N*32] + [8N] morton-as-float
    unsigned N, unsigned nrows)            // nrows = 8N
{
    __shared__ __align__(16) float rec [PPB * 32];   // parent records, 2KB
    __shared__ __align__(16) float tile[PPB * 256];  // feature tile, 16KB
    __shared__ __align__(16) float mort[PPB * 8];    // morton tile, 512B

    const unsigned tid   = threadIdx.x;
    const unsigned pbase = blockIdx.x * PPB;
    const unsigned nP    = (N - pbase < PPB) ? (N - pbase) : PPB;

    // ---- Stage parent records in OUTPUT layout @ stride 32 floats ----
    for (unsigned i = tid; i < nP * 27u; i += TPB) {
        unsigned p = i / 27u, c = i - p * 27u;
        rec[p * 32u + 5u + c] = colors[(pbase + p) * 27u + c];
    }
    if (tid < nP * 3u) {
        unsigned p = tid / 3u, c = tid - p * 3u;
        rec[p * 32u + c] = positions[(pbase + p) * 3u + c];
    }
    if (tid < nP) {
        rec[tid * 32u + 3u] = sizes[pbase + tid];
        rec[tid * 32u + 4u] = densities[pbase + tid];
    }
    __syncthreads();

    const unsigned lane = tid & 31u;
    const unsigned wid  = tid >> 5;

    // ================= Phase A: feature tile in SMEM =================
    {
        const unsigned j  = lane & 7u;     // float4 column of the row
        const unsigned rg = lane >> 3;     // row within 4-row group

        #pragma unroll
        for (unsigned w = 0; w < WP; w++) {
            const unsigned pl = wid * WP + w;
            if (pl >= nP) break;

            const float* r  = &rec[pl * 32u];
            const float4 v  = *reinterpret_cast<const float4*>(r + 4u * j);
            const float4 ps = *reinterpret_cast<const float4*>(r);  // bcast

            const float s  = ps.w;
            const float qd = 0.25f * s;    // exact
            const float hs = 0.5f  * s;    // exact

            float* tb = &tile[pl * 256u];

            #pragma unroll
            for (unsigned t = 0; t < 2; t++) {
                const unsigned oct = 4u * t + rg;
                float4 sv = v;
                if (j == 0u) {
                    sv.x = __fadd_rn(ps.x, (oct & 1u) ? qd : -qd);
                    sv.y = __fadd_rn(ps.y, (oct & 2u) ? qd : -qd);
                    sv.z = __fadd_rn(ps.z, (oct & 4u) ? qd : -qd);
                    sv.w = hs;
                }
                // warp writes lane*16B consecutive: conflict-free STS.128
                *reinterpret_cast<float4*>(tb + oct * 32u + 4u * j) = sv;
            }
        }
    }

    // ================= Phase B: morton tile in SMEM =================
    if (tid < nP * 8u) {
        const unsigned pl  = tid >> 3;
        const unsigned oct = tid & 7u;

        const int   res   = 64 << __ldg(level_p);
        const float fres  = (float)res;
        const int   resm1 = res - 1;

        const float4 ps = *reinterpret_cast<const float4*>(&rec[pl * 32u]);
        const float qd = 0.25f * ps.w;
        float px = __fadd_rn(ps.x, (oct & 1u) ? qd : -qd);
        float py = __fadd_rn(ps.y, (oct & 2u) ? qd : -qd);
        float pz = __fadd_rn(ps.z, (oct & 4u) ? qd : -qd);

        unsigned code = (part1by2(coord_of(pz, fres, resm1)) << 2)
                      + (part1by2(coord_of(py, fres, resm1)) << 1)
                      +  part1by2(coord_of(px, fres, resm1));
        mort[tid] = (float)(int)code;      // exact: code < 2^21 at level 1
    }

    __syncthreads();

    // ================= Bulk copy SMEM -> GMEM via async proxy =================
    if (tid == 0) {
        asm volatile("fence.proxy.async.shared::cta;" ::: "memory");

        const float* gfeat = out + (size_t)pbase * 256u;
        const float* gmort = out + (size_t)nrows * 32u + (size_t)pbase * 8u;
        unsigned feat_bytes = nP * 1024u;  // multiple of 16
        unsigned mort_bytes = nP * 32u;    // multiple of 16

        asm volatile(
            "cp.async.bulk.global.shared::cta.bulk_group [%0], [%1], %2;"
            :: "l"(gfeat), "r"(smem_u32(tile)), "r"(feat_bytes) : "memory");
        asm volatile(
            "cp.async.bulk.global.shared::cta.bulk_group [%0], [%1], %2;"
            :: "l"(gmort), "r"(smem_u32(mort)), "r"(mort_bytes) : "memory");
        asm volatile("cp.async.bulk.commit_group;" ::: "memory");
        // smem may not be reused by the next CTA until TMA has READ it
        asm volatile("cp.async.bulk.wait_group.read 0;" ::: "memory");
    }
}

extern "C" void kernel_launch(void* const* d_in, const int* in_sizes, int n_in,
                              void* d_out, int out_size) {
    const float* positions = (const float*)d_in[0];
    const float* sizes     = (const float*)d_in[1];
    const float* densities = (const float*)d_in[2];
    const float* colors    = (const float*)d_in[3];
    const int*   level     = (const int*)d_in[4];

    unsigned N     = (unsigned)(in_sizes[0] / 3);
    unsigned nrows = N * 8u;

    unsigned blocks = (N + PPB - 1) / PPB;
    asv_expand_kernel<<<blocks, TPB>>>(
        positions, sizes, densities, colors, level,
        (float*)d_out, N, nrows);
}

// round 8
// speedup vs baseline: 1.0582x; 1.0582x over previous
#include <cuda_runtime.h>
#include <cstdint>

// AdaptiveSparseVoxels: expand N parents -> 8N children.
// Output (float32): [8N x 32] row-major features, then 8N morton-as-float.
// Row layout: px py pz size dens c0..c26 (32 floats = 128B)
//
// R8: 256-bit stores (st.global.cs.v8.f32, sm_100a). Lane i -> chunk c=i&3
// (32B = 8 floats of a row), row r=i>>2. ONE warp-op writes one parent's
// entire 8-row block: 1KB fully contiguous. Parent record broadcast from
// smem (output layout, stride 32). Lanes with c==0 substitute child
// pos/size. Morton phase unchanged from R6 (full-lane packed, contiguous
// 1KB store per block).

#define TPB 256
#define WPB 8              // warps per block
#define WP  4              // parents per warp (phase A)
#define PPB (WPB * WP)     // 32 parents per block

__device__ __forceinline__ unsigned part1by2(unsigned n) {
    n &= 1023u;
    n = (n ^ (n << 16)) & 0xFF0000FFu;
    n = (n ^ (n << 8))  & 0x0300F00Fu;
    n = (n ^ (n << 4))  & 0x030C30C3u;
    n = (n ^ (n << 2))  & 0x09249249u;
    return n;
}

__device__ __forceinline__ unsigned coord_of(float p, float fres, int resm1) {
    // reference: ((p + 1) / 2 * res).astype(int32) then clip(0, res-1)
    float norm = __fmul_rn(__fmul_rn(__fadd_rn(p, 1.0f), 0.5f), fres);
    int c = (int)norm;                 // trunc toward zero == astype(int32)
    c = c < 0 ? 0 : (c > resm1 ? resm1 : c);
    return (unsigned)c;
}

__device__ __forceinline__ void stg256_cs(float* gaddr,
                                          float4 a, float4 b) {
    asm volatile(
        "st.global.cs.v8.f32 [%0], {%1,%2,%3,%4,%5,%6,%7,%8};"
        :: "l"(gaddr),
           "f"(a.x), "f"(a.y), "f"(a.z), "f"(a.w),
           "f"(b.x), "f"(b.y), "f"(b.z), "f"(b.w)
        : "memory");
}

__global__ void __launch_bounds__(TPB)
asv_expand_kernel(
    const float* __restrict__ positions,   // [N,3]
    const float* __restrict__ sizes,       // [N]
    const float* __restrict__ densities,   // [N]
    const float* __restrict__ colors,      // [N,27]
    const int*   __restrict__ level_p,     // [1]
    float*       __restrict__ out,         // [8N*32] + [8N] morton-as-float
    unsigned N, unsigned nrows)            // nrows = 8N
{
    __shared__ __align__(32) float rec[PPB * 32];

    const unsigned tid   = threadIdx.x;
    const unsigned pbase = blockIdx.x * PPB;
    const unsigned nP    = (N - pbase < PPB) ? (N - pbase) : PPB;

    // ---- Stage parent records in OUTPUT layout @ stride 32 floats ----
    for (unsigned i = tid; i < nP * 27u; i += TPB) {
        unsigned p = i / 27u, c = i - p * 27u;
        rec[p * 32u + 5u + c] = colors[(pbase + p) * 27u + c];
    }
    if (tid < nP * 3u) {
        unsigned p = tid / 3u, c = tid - p * 3u;
        rec[p * 32u + c] = positions[(pbase + p) * 3u + c];
    }
    if (tid < nP) {
        rec[tid * 32u + 3u] = sizes[pbase + tid];
        rec[tid * 32u + 4u] = densities[pbase + tid];
    }
    __syncthreads();

    const unsigned lane = tid & 31u;
    const unsigned wid  = tid >> 5;

    // ============ Phase A: feature stores, 1 STG.256 per parent ============
    {
        const unsigned c   = lane & 3u;    // 32B chunk of the row (words 8c..)
        const unsigned oct = lane >> 2;    // row 0..7 of the parent

        #pragma unroll
        for (unsigned w = 0; w < WP; w++) {
            const unsigned pl = wid * WP + w;
            if (pl >= nP) break;

            const float* r = &rec[pl * 32u];
            // lane's 8-word chunk (two LDS.128; 4-way broadcast per address)
            float4 v0 = *reinterpret_cast<const float4*>(r + 8u * c + 0u);
            float4 v1 = *reinterpret_cast<const float4*>(r + 8u * c + 4u);
            const float4 ps = *reinterpret_cast<const float4*>(r);  // bcast

            if (c == 0u) {                 // substitute child pos/size
                const float qd = 0.25f * ps.w;       // exact
                v0.x = __fadd_rn(ps.x, (oct & 1u) ? qd : -qd);
                v0.y = __fadd_rn(ps.y, (oct & 2u) ? qd : -qd);
                v0.z = __fadd_rn(ps.z, (oct & 4u) ? qd : -qd);
                v0.w = 0.5f * ps.w;                  // exact
            }

            float* gp = out + (size_t)(pbase + pl) * 256u + oct * 32u + 8u * c;
            stg256_cs(gp, v0, v1);         // warp-op: 1KB contiguous
        }
    }

    // ============ Phase B: morton, full-lane packed ============
    if (tid < nP * 8u) {
        const unsigned pl  = tid >> 3;
        const unsigned oct = tid & 7u;

        const int   res   = 64 << __ldg(level_p);
        const float fres  = (float)res;
        const int   resm1 = res - 1;

        const float4 ps = *reinterpret_cast<const float4*>(&rec[pl * 32u]);
        const float qd = 0.25f * ps.w;
        float px = __fadd_rn(ps.x, (oct & 1u) ? qd : -qd);
        float py = __fadd_rn(ps.y, (oct & 2u) ? qd : -qd);
        float pz = __fadd_rn(ps.z, (oct & 4u) ? qd : -qd);

        unsigned code = (part1by2(coord_of(pz, fres, resm1)) << 2)
                      + (part1by2(coord_of(py, fres, resm1)) << 1)
                      +  part1by2(coord_of(px, fres, resm1));

        __stcs(out + (size_t)nrows * 32u + (size_t)pbase * 8u + tid,
               (float)(int)code);          // exact: code < 2^21 at level 1
    }
}

extern "C" void kernel_launch(void* const* d_in, const int* in_sizes, int n_in,
                              void* d_out, int out_size) {
    const float* positions = (const float*)d_in[0];
    const float* sizes     = (const float*)d_in[1];
    const float* densities = (const float*)d_in[2];
    const float* colors    = (const float*)d_in[3];
    const int*   level     = (const int*)d_in[4];

    unsigned N     = (unsigned)(in_sizes[0] / 3);
    unsigned nrows = N * 8u;

    unsigned blocks = (N + PPB - 1) / PPB;
    asv_expand_kernel<<<blocks, TPB>>>(
        positions, sizes, densities, colors, level,
        (float*)d_out, N, nrows);
}